// round 7
// baseline (speedup 1.0000x reference)
#include <cuda_runtime.h>
#include <cstdint>

#define CN    8192
#define NB    4096
#define NCTA  8
#define NTHR  1024
#define BPC   (NB / NCTA)     // 512 buckets per CTA
#define CAP   32              // slots per bucket (expected max load ~11)

// dynamic smem layout (bytes)
#define OFF_CNT   0                       // 512 u32
#define OFF_BSUM  2048                    // 512 f32
#define OFF_HDR   4096                    // 512 x {f32 suf_excl_local, u32 cnt}
#define OFF_MISC  8192                    // +0 total, +4 partial, +8 sufftot[9]
#define OFF_RED   8320                    // 32 f32 scratch
#define OFF_SLOT  8704                    // 512*CAP*8 = 131072
#define SMEM_BYTES (OFF_SLOT + BPC * CAP * 8)

__device__ __forceinline__ uint32_t smem_u32(const void* p) {
    uint32_t a;
    asm("{ .reg .u64 t; cvta.to.shared.u64 t, %1; cvt.u32.u64 %0, t; }"
        : "=r"(a) : "l"(p));
    return a;
}
__device__ __forceinline__ uint32_t my_rank() {
    uint32_t r; asm("mov.u32 %0, %%cluster_ctarank;" : "=r"(r)); return r;
}
__device__ __forceinline__ uint32_t mapa_u32(uint32_t a, uint32_t r) {
    uint32_t d;
    asm("mapa.shared::cluster.u32 %0, %1, %2;" : "=r"(d) : "r"(a), "r"(r));
    return d;
}
__device__ __forceinline__ uint32_t atom_inc_rc(uint32_t a) {
    uint32_t old;
    asm volatile("atom.relaxed.cluster.shared::cluster.add.u32 %0, [%1], %2;"
                 : "=r"(old) : "r"(a), "r"(1u) : "memory");
    return old;
}
__device__ __forceinline__ void red_add_rc(uint32_t a, float v) {
    asm volatile("red.relaxed.cluster.shared::cluster.add.f32 [%0], %1;"
                 :: "r"(a), "f"(v) : "memory");
}
__device__ __forceinline__ void st64_rc(uint32_t a, float x, float y) {
    uint64_t p;
    asm("mov.b64 %0, {%1, %2};" : "=l"(p)
        : "r"(__float_as_uint(x)), "r"(__float_as_uint(y)));
    asm volatile("st.shared::cluster.b64 [%0], %1;" :: "r"(a), "l"(p) : "memory");
}
__device__ __forceinline__ void ld64_rc(uint32_t a, uint32_t& x, uint32_t& y) {
    uint64_t p;
    asm volatile("ld.shared::cluster.b64 %0, [%1];" : "=l"(p) : "r"(a) : "memory");
    asm("mov.b64 {%0, %1}, %2;" : "=r"(x), "=r"(y) : "l"(p));
}
__device__ __forceinline__ float ld32_rc(uint32_t a) {
    float v;
    asm volatile("ld.shared::cluster.f32 %0, [%1];" : "=f"(v) : "r"(a) : "memory");
    return v;
}
// barrier.cluster.arrive has release, .wait has acquire semantics (cluster scope),
// which orders the relaxed DSMEM atomics/stores above it.
#define CSYNC() do { \
    asm volatile("barrier.cluster.arrive.aligned;" ::: "memory"); \
    asm volatile("barrier.cluster.wait.aligned;"   ::: "memory"); \
} while (0)

// Monotone bucket map: b_j > b_i => sv_j > sv_i ; b_j < b_i => sv_j < sv_i.
__device__ __forceinline__ int bkt(float v) {
    float x = v * (float)NB;
    x = fminf(fmaxf(x, 0.0f), (float)(NB - 1));
    return (int)x;
}

__global__ void __launch_bounds__(NTHR, 1) __cluster_dims__(NCTA, 1, 1)
cox_cluster_kernel(const float* __restrict__ theta,
                   const float* __restrict__ sv,
                   const float* __restrict__ cen,
                   float* __restrict__ out)
{
    extern __shared__ char sm[];
    const uint32_t base = smem_u32(sm);
    uint32_t* s_cnt   = (uint32_t*)(sm + OFF_CNT);
    float*    s_bsum  = (float*)   (sm + OFF_BSUM);
    float2*   s_hdr   = (float2*)  (sm + OFF_HDR);
    float*    s_misc  = (float*)   (sm + OFF_MISC);   // [0]=total [1]=partial [2..10]=sufftot
    float*    s_red   = (float*)   (sm + OFF_RED);

    const int tid  = threadIdx.x;
    const int lane = tid & 31;
    const int wid  = tid >> 5;
    const uint32_t rank = my_rank();
    const int gid = rank * NTHR + tid;          // 0..8191

    // ---- loads + exp (overlap with zero/sync) ----
    const float v  = sv[gid];
    const float th = theta[gid];
    const float ce = cen[gid];
    const float e  = __expf(th);

    // ---- zero own bucket state ----
    if (tid < BPC)               s_cnt[tid] = 0u;
    else if (tid < 2 * BPC)      s_bsum[tid - BPC] = 0.0f;
    CSYNC();                                        // C1: all zeroed, all CTAs alive

    // ---- insert into owner CTA ----
    const int b     = bkt(v);
    const int owner = b >> 9;                       // /512
    const int lb    = b & (BPC - 1);
    {
        uint32_t p = atom_inc_rc(mapa_u32(base + OFF_CNT + lb * 4, owner));
        if (p < CAP)
            st64_rc(mapa_u32(base + OFF_SLOT + (lb * CAP + p) * 8, owner), v, e);
        red_add_rc(mapa_u32(base + OFF_BSUM + lb * 4, owner), e);
    }
    CSYNC();                                        // C2: all inserts landed

    // ---- local suffix scan over 512 bucket sums (reversed-index scan) ----
    float val = 0.0f;
    const int lb_s = (BPC - 1) - tid;               // bucket handled when tid<512
    if (tid < BPC) val = s_bsum[lb_s];
    #pragma unroll
    for (int o = 1; o < 32; o <<= 1) {
        float n = __shfl_up_sync(0xffffffffu, val, o);
        if (lane >= o) val += n;
    }
    if (lane == 31 && wid < 16) s_red[wid] = val;
    __syncthreads();
    if (tid < 16) {
        float w = s_red[tid];
        #pragma unroll
        for (int o = 1; o < 16; o <<= 1) {
            float n = __shfl_up_sync(0x0000ffffu, w, o);
            if (tid >= o) w += n;
        }
        s_red[tid] = w;
    }
    __syncthreads();
    if (tid < BPC) {
        float pre      = wid ? s_red[wid - 1] : 0.0f;
        float suf_incl = val + pre;                 // local suffix incl. own bucket
        unsigned c = s_cnt[lb_s]; if (c > CAP) c = CAP;
        s_hdr[lb_s] = make_float2(suf_incl - s_bsum[lb_s], __uint_as_float(c));
    }
    if (tid == 0) s_misc[0] = s_red[15];            // this CTA's total
    CSYNC();                                        // C3: hdr + totals visible

    // ---- fetch all 8 CTA totals, build suffix-of-totals locally ----
    if (tid == 0) {
        float t[NCTA];
        #pragma unroll
        for (int q = 0; q < NCTA; q++)
            t[q] = ld32_rc(mapa_u32(base + OFF_MISC, q));
        float run = 0.0f;
        s_misc[2 + NCTA] = 0.0f;
        #pragma unroll
        for (int q = NCTA - 1; q >= 0; q--) { run += t[q]; s_misc[2 + q] = run; }
    }
    __syncthreads();

    // ---- per-row compute (1 row / thread) ----
    uint32_t hx, hy;
    ld64_rc(mapa_u32(base + OFF_HDR + lb * 8, owner), hx, hy);
    float    suf = __uint_as_float(hx) + s_misc[2 + owner + 1];
    unsigned cnt = hy;
    float w = 0.0f;
    {
        uint32_t sa = mapa_u32(base + OFF_SLOT + lb * CAP * 8, owner);
        for (unsigned m = 0; m < cnt; m++) {
            uint32_t ax, ay;
            ld64_rc(sa + m * 8, ax, ay);
            if (__uint_as_float(ax) >= v) w += __uint_as_float(ay);
        }
    }
    float risk = suf + w;
    float acc  = (th - __logf(risk)) * ce;

    // ---- CTA reduce ----
    #pragma unroll
    for (int o = 16; o > 0; o >>= 1) acc += __shfl_xor_sync(0xffffffffu, acc, o);
    if (lane == 0) s_red[wid] = acc;                // 32 warps
    __syncthreads();
    if (tid < 32) {
        float x = s_red[tid];
        #pragma unroll
        for (int o = 16; o > 0; o >>= 1) x += __shfl_xor_sync(0xffffffffu, x, o);
        if (tid == 0) s_misc[1] = x;                // CTA partial
    }
    CSYNC();                                        // C4: partials visible, peers alive

    if (rank == 0 && tid == 0) {
        float s = 0.0f;
        #pragma unroll
        for (int q = 0; q < NCTA; q++)
            s += ld32_rc(mapa_u32(base + OFF_MISC + 4, q));
        out[0] = -s / (float)CN;
    }

    CSYNC();   // C5: keep ALL CTAs alive until rank 0 finished reading peer SMEM
}

extern "C" void kernel_launch(void* const* d_in, const int* in_sizes, int n_in,
                              void* d_out, int out_size) {
    const float* hazard_pred = (const float*)d_in[0];
    const float* survtime    = (const float*)d_in[1];
    const float* censor      = (const float*)d_in[2];
    float* out = (float*)d_out;

    cudaFuncSetAttribute(cox_cluster_kernel,
                         cudaFuncAttributeMaxDynamicSharedMemorySize, SMEM_BYTES);
    cox_cluster_kernel<<<NCTA, NTHR, SMEM_BYTES>>>(hazard_pred, survtime, censor, out);
}

// round 8
// speedup vs baseline: 1.6118x; 1.6118x over previous
#include <cuda_runtime.h>
#include <cstdint>

#define CN    8192
#define NB    4096
#define CAP   16
#define OVCAP 512
#define K2B   16          // K2 blocks
#define K2T   512         // K2 threads per block

// All state is zero at module load; K2's last block restores it to zero
// after every call (self-cleaning), so no zeroing kernel is needed.
__device__ int      g_cnt[NB];
__device__ float    g_bsum[NB];
__device__ float2   g_slot[NB * CAP];
__device__ float2   g_ovf[OVCAP];
__device__ int      g_ovf_cnt;
__device__ float    g_accum;
__device__ unsigned g_done;

// Monotone bucket map: b_j > b_i => sv_j > sv_i ; b_j < b_i => sv_j < sv_i.
__device__ __forceinline__ int bkt(float v) {
    float x = v * (float)NB;
    x = fminf(fmaxf(x, 0.0f), (float)(NB - 1));
    return (int)x;
}

// ---- K1: exp + bucket insert (state guaranteed zero at entry) ----
__global__ void __launch_bounds__(128) k1_insert(
    const float* __restrict__ theta,
    const float* __restrict__ sv)
{
    int i = blockIdx.x * 128 + threadIdx.x;       // 0..8191
    float v = sv[i];
    float e = __expf(theta[i]);
    int b = bkt(v);
    int p = atomicAdd(&g_cnt[b], 1);
    if (p < CAP) {
        g_slot[b * CAP + p] = make_float2(v, e);
        atomicAdd(&g_bsum[b], e);                 // REDG, no return
    } else {
        int q = atomicAdd(&g_ovf_cnt, 1);         // robustness path (expected 0)
        if (q < OVCAP) g_ovf[q] = make_float2(v, e);
    }
}

// ---- K2: suffix scan + per-row compute + last-block finalize/cleanup ----
__global__ void __launch_bounds__(K2T) k2_compute(
    const float* __restrict__ theta,
    const float* __restrict__ sv,
    const float* __restrict__ cen,
    float* __restrict__ out)
{
    __shared__ float s_suf[NB + 1];
    __shared__ float s_w[16];
    __shared__ int   s_last;

    const int t    = threadIdx.x;
    const int lane = t & 31;
    const int wid  = t >> 5;

    // -- suffix scan over 4096 bucket sums (each thread owns 8, reversed) --
    const int c = (K2T - 1) - t;                  // chunk index, reversed order
    float g[8];
    {
        const float4* bs4 = reinterpret_cast<const float4*>(g_bsum);
        float4 f0 = bs4[c * 2 + 0];
        float4 f1 = bs4[c * 2 + 1];
        g[0] = f0.x; g[1] = f0.y; g[2] = f0.z; g[3] = f0.w;
        g[4] = f1.x; g[5] = f1.y; g[6] = f1.z; g[7] = f1.w;
    }
    float gs = g[0] + g[1] + g[2] + g[3] + g[4] + g[5] + g[6] + g[7];

    // inclusive scan over t (t ascending == chunks descending == suffix)
    float val = gs;
    #pragma unroll
    for (int o = 1; o < 32; o <<= 1) {
        float n = __shfl_up_sync(0xffffffffu, val, o);
        if (lane >= o) val += n;
    }
    if (lane == 31) s_w[wid] = val;
    __syncthreads();
    if (t < 16) {
        float wv = s_w[t];
        #pragma unroll
        for (int o = 1; o < 16; o <<= 1) {
            float n = __shfl_up_sync(0x0000ffffu, wv, o);
            if (t >= o) wv += n;
        }
        s_w[t] = wv;
    }
    __syncthreads();
    val += (wid > 0) ? s_w[wid - 1] : 0.0f;       // suffix INCLUDING own chunk

    float run = val - gs;                         // suffix of strictly-later chunks
    #pragma unroll
    for (int i = 7; i >= 0; i--) {
        run += g[i];
        s_suf[c * 8 + i] = run;                   // suffix including bucket c*8+i
    }
    if (t == 0) { s_suf[NB] = 0.0f; s_last = 0; }
    __syncthreads();

    // -- one row per thread --
    const int r   = blockIdx.x * K2T + t;         // 0..8191
    const float v = sv[r];
    const int   b = bkt(v);

    int cnt = g_cnt[b];
    cnt = cnt < CAP ? cnt : CAP;
    float w = 0.0f;
    const float2* sl = &g_slot[b * CAP];
    for (int m = 0; m < cnt; m++) {
        float2 s = sl[m];
        if (s.x >= v) w += s.y;
    }
    int L = g_ovf_cnt;                            // expected 0
    L = L < OVCAP ? L : OVCAP;
    for (int m = 0; m < L; m++) {
        float2 s = g_ovf[m];
        if (s.x >= v) w += s.y;
    }

    float risk = s_suf[b + 1] + w;
    float acc  = (theta[r] - __logf(risk)) * cen[r];

    // -- block reduce --
    #pragma unroll
    for (int o = 16; o > 0; o >>= 1) acc += __shfl_xor_sync(0xffffffffu, acc, o);
    if (lane == 0) s_w[wid] = acc;
    __syncthreads();
    if (t == 0) {
        float p = 0.0f;
        #pragma unroll
        for (int q = 0; q < 16; q++) p += s_w[q];
        atomicAdd(&g_accum, p);
        __threadfence();
        unsigned old = atomicAdd(&g_done, 1u);
        if (old == K2B - 1) s_last = 1;           // this block is last; all reads done
    }
    __syncthreads();

    // -- last block: write output + restore all state to zero --
    if (s_last) {
        if (t == 0) {
            out[0] = -(*(volatile float*)&g_accum) / (float)CN;
            g_accum   = 0.0f;
            g_ovf_cnt = 0;
            g_done    = 0u;
        }
        #pragma unroll
        for (int i = 0; i < NB / K2T; i++) {      // 8 each
            g_cnt [t + i * K2T] = 0;
            g_bsum[t + i * K2T] = 0.0f;
        }
    }
}

extern "C" void kernel_launch(void* const* d_in, const int* in_sizes, int n_in,
                              void* d_out, int out_size) {
    const float* hazard_pred = (const float*)d_in[0];
    const float* survtime    = (const float*)d_in[1];
    const float* censor      = (const float*)d_in[2];
    float* out = (float*)d_out;

    k1_insert <<<CN / 128, 128>>>(hazard_pred, survtime);
    k2_compute<<<K2B, K2T>>>(hazard_pred, survtime, censor, out);
}

// round 9
// speedup vs baseline: 1.9582x; 1.2149x over previous
#include <cuda_runtime.h>
#include <cstdint>

#define CN    8192
#define NB    4096
#define CAP   16
#define OVCAP 512
#define K1B   32
#define K1T   256
#define K2B   16
#define K2T   512

// All state is zero at module load; K2's last block restores it to zero
// after every call (self-cleaning), so no zeroing kernel is needed.
__device__ int      g_cnt[NB];
__device__ float    g_bsum[NB];
__device__ float2   g_slot[NB * CAP];   // one bucket = 128B = one cache line
__device__ float2   g_ovf[OVCAP];
__device__ int      g_ovf_cnt;
__device__ float    g_accum;
__device__ unsigned g_done;

// Monotone bucket map: b_j > b_i => sv_j > sv_i ; b_j < b_i => sv_j < sv_i.
__device__ __forceinline__ int bkt(float v) {
    float x = v * (float)NB;
    x = fminf(fmaxf(x, 0.0f), (float)(NB - 1));
    return (int)x;
}

// ---- K1: exp + bucket insert (state guaranteed zero at entry) ----
__global__ void __launch_bounds__(K1T) k1_insert(
    const float* __restrict__ theta,
    const float* __restrict__ sv)
{
    // Let the dependent kernel start launching immediately.
    cudaTriggerProgrammaticLaunchCompletion();

    int i = blockIdx.x * K1T + threadIdx.x;       // 0..8191
    float v = sv[i];
    float e = __expf(theta[i]);
    int b = bkt(v);
    int p = atomicAdd(&g_cnt[b], 1);
    if (p < CAP) {
        g_slot[b * CAP + p] = make_float2(v, e);
        atomicAdd(&g_bsum[b], e);                 // REDG, no return
    } else {
        int q = atomicAdd(&g_ovf_cnt, 1);         // robustness path (expected 0)
        if (q < OVCAP) g_ovf[q] = make_float2(v, e);
    }
}

// ---- K2: suffix scan + per-row compute + last-block finalize/cleanup ----
__global__ void __launch_bounds__(K2T) k2_compute(
    const float* __restrict__ theta,
    const float* __restrict__ sv,
    const float* __restrict__ cen,
    float* __restrict__ out)
{
    __shared__ float s_suf[NB + 1];
    __shared__ float s_w[16];
    __shared__ int   s_last;

    const int t    = threadIdx.x;
    const int lane = t & 31;
    const int wid  = t >> 5;

    // ---- pre-sync phase: inputs K1 does not write (overlaps K1 via PDL) ----
    const int   r  = blockIdx.x * K2T + t;        // 0..8191
    const float v  = sv[r];
    const float th = theta[r];
    const float ce = cen[r];
    const int   b  = bkt(v);

    // ---- wait for K1's memory to be visible ----
    cudaGridDependencySynchronize();

    // ---- prefetch row-local K1 outputs; complete under the scan below ----
    const int cnt_raw = g_cnt[b];
    const float4* sl4 = reinterpret_cast<const float4*>(&g_slot[b * CAP]);
    const float4 sA = sl4[0];                     // slots 0,1
    const float4 sB = sl4[1];                     // slots 2,3
    const int ovl_raw = g_ovf_cnt;

    // ---- suffix scan over 4096 bucket sums (each thread owns 8, reversed) --
    const int c = (K2T - 1) - t;                  // chunk index, reversed order
    float g[8];
    {
        const float4* bs4 = reinterpret_cast<const float4*>(g_bsum);
        float4 f0 = bs4[c * 2 + 0];
        float4 f1 = bs4[c * 2 + 1];
        g[0] = f0.x; g[1] = f0.y; g[2] = f0.z; g[3] = f0.w;
        g[4] = f1.x; g[5] = f1.y; g[6] = f1.z; g[7] = f1.w;
    }
    float gs = g[0] + g[1] + g[2] + g[3] + g[4] + g[5] + g[6] + g[7];

    float val = gs;                               // inclusive scan (t asc = suffix)
    #pragma unroll
    for (int o = 1; o < 32; o <<= 1) {
        float n = __shfl_up_sync(0xffffffffu, val, o);
        if (lane >= o) val += n;
    }
    if (lane == 31) s_w[wid] = val;
    __syncthreads();
    if (t < 16) {
        float wv = s_w[t];
        #pragma unroll
        for (int o = 1; o < 16; o <<= 1) {
            float n = __shfl_up_sync(0x0000ffffu, wv, o);
            if (t >= o) wv += n;
        }
        s_w[t] = wv;
    }
    __syncthreads();
    val += (wid > 0) ? s_w[wid - 1] : 0.0f;       // suffix INCLUDING own chunk

    float run = val - gs;                         // suffix of strictly-later chunks
    #pragma unroll
    for (int i = 7; i >= 0; i--) {
        run += g[i];
        s_suf[c * 8 + i] = run;                   // suffix including bucket c*8+i
    }
    if (t == 0) { s_suf[NB] = 0.0f; s_last = 0; }
    __syncthreads();

    // ---- combine: same-bucket exact part (prefetched) + suffix ----
    const int cnt = cnt_raw < CAP ? cnt_raw : CAP;
    float w = 0.0f;
    if (cnt > 0 && sA.x >= v) w += sA.y;
    if (cnt > 1 && sA.z >= v) w += sA.w;
    if (cnt > 2 && sB.x >= v) w += sB.y;
    if (cnt > 3 && sB.z >= v) w += sB.w;
    const float2* sl = &g_slot[b * CAP];
    for (int m = 4; m < cnt; m++) {               // rare (P ≈ 5%)
        float2 s = sl[m];
        if (s.x >= v) w += s.y;
    }
    int L = ovl_raw < OVCAP ? ovl_raw : OVCAP;    // expected 0
    for (int m = 0; m < L; m++) {
        float2 s = g_ovf[m];
        if (s.x >= v) w += s.y;
    }

    float risk = s_suf[b + 1] + w;
    float acc  = (th - __logf(risk)) * ce;

    // ---- block reduce ----
    #pragma unroll
    for (int o = 16; o > 0; o >>= 1) acc += __shfl_xor_sync(0xffffffffu, acc, o);
    if (lane == 0) s_w[wid] = acc;
    __syncthreads();
    if (t == 0) {
        float p = 0.0f;
        #pragma unroll
        for (int q = 0; q < 16; q++) p += s_w[q];
        atomicAdd(&g_accum, p);
        __threadfence();
        unsigned old = atomicAdd(&g_done, 1u);
        if (old == K2B - 1) s_last = 1;           // all blocks done reading state
    }
    __syncthreads();

    // ---- last block: write output + restore all state to zero ----
    if (s_last) {
        if (t == 0) {
            out[0] = -(*(volatile float*)&g_accum) / (float)CN;
            g_accum   = 0.0f;
            g_ovf_cnt = 0;
            g_done    = 0u;
        }
        #pragma unroll
        for (int i = 0; i < NB / K2T; i++) {      // 8 each
            g_cnt [t + i * K2T] = 0;
            g_bsum[t + i * K2T] = 0.0f;
        }
    }
}

extern "C" void kernel_launch(void* const* d_in, const int* in_sizes, int n_in,
                              void* d_out, int out_size) {
    const float* hazard_pred = (const float*)d_in[0];
    const float* survtime    = (const float*)d_in[1];
    const float* censor      = (const float*)d_in[2];
    float* out = (float*)d_out;

    k1_insert<<<K1B, K1T>>>(hazard_pred, survtime);

    // K2 launched with Programmatic Stream Serialization: it starts while K1
    // runs and self-synchronizes via cudaGridDependencySynchronize().
    cudaLaunchConfig_t cfg = {};
    cfg.gridDim  = dim3(K2B);
    cfg.blockDim = dim3(K2T);
    cfg.dynamicSmemBytes = 0;
    cfg.stream = 0;
    cudaLaunchAttribute attrs[1];
    attrs[0].id = cudaLaunchAttributeProgrammaticStreamSerialization;
    attrs[0].val.programmaticStreamSerializationAllowed = 1;
    cfg.attrs = attrs;
    cfg.numAttrs = 1;
    cudaLaunchKernelEx(&cfg, k2_compute, hazard_pred, survtime, censor, out);
}